// round 6
// baseline (speedup 1.0000x reference)
#include <cuda_runtime.h>

// ---------------------------------------------------------------------------
// GAT 3-layer forward. CSR build overlapped with layer-0 GEMM on a side
// stream; per layer: GEMM(+fused att dots) -> single-pass aggregation.
// Layers 0/1 use a 128x128-tile GEMM (8x8/thread, FMA-bound); layer 2 uses
// the 64x64 kernel (N=64).
// ---------------------------------------------------------------------------

#define MAXN 10240
#define MAXE 340000

__device__ float g_H[MAXN * 256];
__device__ float g_X[MAXN * 256];
__device__ float g_as[MAXN * 4];
__device__ float g_ad[MAXN * 4];
__device__ int   g_cnt[MAXN];
__device__ int   g_off[MAXN + 1];
__device__ int   g_wp[MAXN];
__device__ int   g_csr_src[MAXE];

// ---------------------------------------------------------------------------
// GEMM 128x128 tile, 256 threads, 8x8 per thread, BK=16, register prefetch.
// Fused attention-dot epilogue; tile spans 2 heads (64 cols each):
// head = blockIdx.y*2 + (tx>>3).
// ---------------------------------------------------------------------------
__global__ void __launch_bounds__(256) gemm128att(
    const float* __restrict__ A, const float* __restrict__ B,
    float* __restrict__ C,
    const float* __restrict__ asw, const float* __restrict__ adw,
    float* __restrict__ as_o, float* __restrict__ ad_o,
    int M, int N, int K, int heads)
{
    __shared__ float As[16][132];
    __shared__ float Bs[16][132];
    int tid = threadIdx.x;              // 256
    int tx = tid & 15, ty = tid >> 4;   // 8-col group, 8-row group
    int row0 = blockIdx.x * 128, col0 = blockIdx.y * 128;

    // A tile 128x16 = 512 float4; B tile 16x128 = 512 float4; 2 each/thread
    int ar0 = tid >> 2,          akq0 = (tid & 3) * 4;
    int ar1 = (tid + 256) >> 2,  akq1 = ((tid + 256) & 3) * 4;
    int bk0 = tid >> 5,          bcq0 = (tid & 31) * 4;
    int bk1 = (tid + 256) >> 5,  bcq1 = bcq0;

    float4 ap0, ap1, bp0, bp1;
    {
        int g0 = row0 + ar0, g1 = row0 + ar1;
        ap0 = (g0 < M) ? *reinterpret_cast<const float4*>(A + (size_t)g0 * K + akq0)
                       : make_float4(0.f, 0.f, 0.f, 0.f);
        ap1 = (g1 < M) ? *reinterpret_cast<const float4*>(A + (size_t)g1 * K + akq1)
                       : make_float4(0.f, 0.f, 0.f, 0.f);
        bp0 = *reinterpret_cast<const float4*>(B + (size_t)bk0 * N + col0 + bcq0);
        bp1 = *reinterpret_cast<const float4*>(B + (size_t)bk1 * N + col0 + bcq1);
    }

    float acc[8][8] = {};

    for (int k0 = 0; k0 < K; k0 += 16) {
        As[akq0 + 0][ar0] = ap0.x; As[akq0 + 1][ar0] = ap0.y;
        As[akq0 + 2][ar0] = ap0.z; As[akq0 + 3][ar0] = ap0.w;
        As[akq1 + 0][ar1] = ap1.x; As[akq1 + 1][ar1] = ap1.y;
        As[akq1 + 2][ar1] = ap1.z; As[akq1 + 3][ar1] = ap1.w;
        *reinterpret_cast<float4*>(&Bs[bk0][bcq0]) = bp0;
        *reinterpret_cast<float4*>(&Bs[bk1][bcq1]) = bp1;
        __syncthreads();

        if (k0 + 16 < K) {
            int g0 = row0 + ar0, g1 = row0 + ar1;
            int kn = k0 + 16;
            ap0 = (g0 < M) ? *reinterpret_cast<const float4*>(A + (size_t)g0 * K + kn + akq0)
                           : make_float4(0.f, 0.f, 0.f, 0.f);
            ap1 = (g1 < M) ? *reinterpret_cast<const float4*>(A + (size_t)g1 * K + kn + akq1)
                           : make_float4(0.f, 0.f, 0.f, 0.f);
            bp0 = *reinterpret_cast<const float4*>(B + (size_t)(kn + bk0) * N + col0 + bcq0);
            bp1 = *reinterpret_cast<const float4*>(B + (size_t)(kn + bk1) * N + col0 + bcq1);
        }

        #pragma unroll
        for (int kk = 0; kk < 16; kk++) {
            float4 a0 = *reinterpret_cast<const float4*>(&As[kk][ty * 8]);
            float4 a1 = *reinterpret_cast<const float4*>(&As[kk][ty * 8 + 4]);
            float4 b0 = *reinterpret_cast<const float4*>(&Bs[kk][tx * 8]);
            float4 b1 = *reinterpret_cast<const float4*>(&Bs[kk][tx * 8 + 4]);
            float av[8] = {a0.x, a0.y, a0.z, a0.w, a1.x, a1.y, a1.z, a1.w};
            float bv[8] = {b0.x, b0.y, b0.z, b0.w, b1.x, b1.y, b1.z, b1.w};
            #pragma unroll
            for (int i = 0; i < 8; i++)
                #pragma unroll
                for (int j = 0; j < 8; j++)
                    acc[i][j] += av[i] * bv[j];
        }
        __syncthreads();
    }

    // C store
    #pragma unroll
    for (int i = 0; i < 8; i++) {
        int gr = row0 + ty * 8 + i;
        if (gr < M) {
            float4 v0 = make_float4(acc[i][0], acc[i][1], acc[i][2], acc[i][3]);
            float4 v1 = make_float4(acc[i][4], acc[i][5], acc[i][6], acc[i][7]);
            *reinterpret_cast<float4*>(C + (size_t)gr * N + col0 + tx * 8)     = v0;
            *reinterpret_cast<float4*>(C + (size_t)gr * N + col0 + tx * 8 + 4) = v1;
        }
    }

    // fused attention dots; this thread's cols all belong to head h
    float asv[8], adv_[8];
    #pragma unroll
    for (int j = 0; j < 8; j++) {
        asv[j]  = asw[col0 + tx * 8 + j];
        adv_[j] = adw[col0 + tx * 8 + j];
    }
    int h = blockIdx.y * 2 + (tx >> 3);
    #pragma unroll
    for (int i = 0; i < 8; i++) {
        float ss = 0.f, sd = 0.f;
        #pragma unroll
        for (int j = 0; j < 8; j++) {
            ss += acc[i][j] * asv[j];
            sd += acc[i][j] * adv_[j];
        }
        #pragma unroll
        for (int o = 1; o <= 4; o <<= 1) {   // reduce within 8-lane groups
            ss += __shfl_xor_sync(0xffffffffu, ss, o);
            sd += __shfl_xor_sync(0xffffffffu, sd, o);
        }
        if ((tx & 7) == 0) {
            int gr = row0 + ty * 8 + i;
            if (gr < M) {
                as_o[gr * heads + h] = ss;
                ad_o[gr * heads + h] = sd;
            }
        }
    }
}

// ---------------------------------------------------------------------------
// GEMM 64x64 tile, 128 threads, 8x4/thread (layer 2, N=64).
// ---------------------------------------------------------------------------
__global__ void __launch_bounds__(128) gemm64att(
    const float* __restrict__ A, const float* __restrict__ B,
    float* __restrict__ C,
    const float* __restrict__ asw, const float* __restrict__ adw,
    float* __restrict__ as_o, float* __restrict__ ad_o,
    int M, int N, int K, int heads)
{
    __shared__ float As[16][68];
    __shared__ float Bs[16][68];
    int tid = threadIdx.x;          // 128
    int tx = tid & 15, ty = tid >> 4;
    int row0 = blockIdx.x * 64, col0 = blockIdx.y * 64;

    int ar0 = tid >> 2,          akq0 = (tid & 3) * 4;
    int ar1 = (tid + 128) >> 2,  akq1 = ((tid + 128) & 3) * 4;
    int bk0 = tid >> 4,          bcq0 = (tid & 15) * 4;
    int bk1 = (tid + 128) >> 4,  bcq1 = bcq0;

    float4 ap0, ap1, bp0, bp1;
    {
        int g0 = row0 + ar0, g1 = row0 + ar1;
        ap0 = (g0 < M) ? *reinterpret_cast<const float4*>(A + (size_t)g0 * K + akq0)
                       : make_float4(0.f, 0.f, 0.f, 0.f);
        ap1 = (g1 < M) ? *reinterpret_cast<const float4*>(A + (size_t)g1 * K + akq1)
                       : make_float4(0.f, 0.f, 0.f, 0.f);
        bp0 = *reinterpret_cast<const float4*>(B + (size_t)bk0 * N + col0 + bcq0);
        bp1 = *reinterpret_cast<const float4*>(B + (size_t)bk1 * N + col0 + bcq1);
    }

    float acc[8][4] = {};

    for (int k0 = 0; k0 < K; k0 += 16) {
        As[akq0 + 0][ar0] = ap0.x; As[akq0 + 1][ar0] = ap0.y;
        As[akq0 + 2][ar0] = ap0.z; As[akq0 + 3][ar0] = ap0.w;
        As[akq1 + 0][ar1] = ap1.x; As[akq1 + 1][ar1] = ap1.y;
        As[akq1 + 2][ar1] = ap1.z; As[akq1 + 3][ar1] = ap1.w;
        *reinterpret_cast<float4*>(&Bs[bk0][bcq0]) = bp0;
        *reinterpret_cast<float4*>(&Bs[bk1][bcq1]) = bp1;
        __syncthreads();

        if (k0 + 16 < K) {
            int g0 = row0 + ar0, g1 = row0 + ar1;
            int kn = k0 + 16;
            ap0 = (g0 < M) ? *reinterpret_cast<const float4*>(A + (size_t)g0 * K + kn + akq0)
                           : make_float4(0.f, 0.f, 0.f, 0.f);
            ap1 = (g1 < M) ? *reinterpret_cast<const float4*>(A + (size_t)g1 * K + kn + akq1)
                           : make_float4(0.f, 0.f, 0.f, 0.f);
            bp0 = *reinterpret_cast<const float4*>(B + (size_t)(kn + bk0) * N + col0 + bcq0);
            bp1 = *reinterpret_cast<const float4*>(B + (size_t)(kn + bk1) * N + col0 + bcq1);
        }

        #pragma unroll
        for (int kk = 0; kk < 16; kk++) {
            float4 a0 = *reinterpret_cast<const float4*>(&As[kk][ty * 8]);
            float4 a1 = *reinterpret_cast<const float4*>(&As[kk][ty * 8 + 4]);
            float4 b4 = *reinterpret_cast<const float4*>(&Bs[kk][tx * 4]);
            float av[8] = {a0.x, a0.y, a0.z, a0.w, a1.x, a1.y, a1.z, a1.w};
            float bv[4] = {b4.x, b4.y, b4.z, b4.w};
            #pragma unroll
            for (int i = 0; i < 8; i++)
                #pragma unroll
                for (int j = 0; j < 4; j++)
                    acc[i][j] += av[i] * bv[j];
        }
        __syncthreads();
    }

    #pragma unroll
    for (int i = 0; i < 8; i++) {
        int gr = row0 + ty * 8 + i;
        if (gr < M) {
            float4 v = make_float4(acc[i][0], acc[i][1], acc[i][2], acc[i][3]);
            *reinterpret_cast<float4*>(C + (size_t)gr * N + col0 + tx * 4) = v;
        }
    }

    float asv[4], adv_[4];
    #pragma unroll
    for (int j = 0; j < 4; j++) {
        asv[j]  = asw[col0 + tx * 4 + j];
        adv_[j] = adw[col0 + tx * 4 + j];
    }
    int h = blockIdx.y;
    #pragma unroll
    for (int i = 0; i < 8; i++) {
        float ss = 0.f, sd = 0.f;
        #pragma unroll
        for (int j = 0; j < 4; j++) {
            ss += acc[i][j] * asv[j];
            sd += acc[i][j] * adv_[j];
        }
        #pragma unroll
        for (int o = 1; o <= 8; o <<= 1) {
            ss += __shfl_xor_sync(0xffffffffu, ss, o);
            sd += __shfl_xor_sync(0xffffffffu, sd, o);
        }
        if (tx == 0) {
            int gr = row0 + ty * 8 + i;
            if (gr < M) {
                as_o[gr * heads + h] = ss;
                ad_o[gr * heads + h] = sd;
            }
        }
    }
}

// ---------------------------------------------------------------------------
// CSR build
// ---------------------------------------------------------------------------
__global__ void zero_cnt(int N)
{
    int i = blockIdx.x * blockDim.x + threadIdx.x;
    if (i < N) g_cnt[i] = 0;
}

__global__ void hist_k(const int* __restrict__ ei, int E, int Etot)
{
    int e = blockIdx.x * blockDim.x + threadIdx.x;
    if (e >= Etot) return;
    int d = (e < E) ? ei[E + e] : (e - E);
    atomicAdd(&g_cnt[d], 1);
}

__global__ void scan_k(int N, int Etot)
{
    __shared__ int wsum[32];
    int tid = threadIdx.x;
    const int PER = 12;
    int base = tid * PER;
    int loc[PER];
    int s = 0;
    #pragma unroll
    for (int i = 0; i < PER; i++) {
        int idx = base + i;
        int v = (idx < N) ? g_cnt[idx] : 0;
        loc[i] = s; s += v;
    }
    int lane = tid & 31, wid = tid >> 5;
    int x = s;
    #pragma unroll
    for (int o = 1; o < 32; o <<= 1) {
        int y = __shfl_up_sync(0xffffffffu, x, o);
        if (lane >= o) x += y;
    }
    if (lane == 31) wsum[wid] = x;
    __syncthreads();
    if (wid == 0) {
        int w = wsum[lane];
        #pragma unroll
        for (int o = 1; o < 32; o <<= 1) {
            int y = __shfl_up_sync(0xffffffffu, w, o);
            if (lane >= o) w += y;
        }
        wsum[lane] = w;
    }
    __syncthreads();
    int excl = x - s + (wid ? wsum[wid - 1] : 0);
    #pragma unroll
    for (int i = 0; i < PER; i++) {
        int idx = base + i;
        if (idx < N) { int v = excl + loc[i]; g_off[idx] = v; g_wp[idx] = v; }
    }
    if (tid == 0) g_off[N] = Etot;
}

__global__ void scatter_k(const int* __restrict__ ei, int E, int Etot)
{
    int e = blockIdx.x * blockDim.x + threadIdx.x;
    if (e >= Etot) return;
    int sIdx, d;
    if (e < E) { sIdx = ei[e]; d = ei[E + e]; } else { sIdx = d = e - E; }
    int pos = atomicAdd(&g_wp[d], 1);
    g_csr_src[pos] = sIdx;
}

// ---------------------------------------------------------------------------
// Single-pass aggregation, heads=4, C=64 (256 ch). One block/node, 128 thr.
// ---------------------------------------------------------------------------
__global__ void __launch_bounds__(128) agg4(
    const float* __restrict__ H, const float* __restrict__ as,
    const float* __restrict__ ad, const float* __restrict__ bias,
    const float* __restrict__ gam, const float* __restrict__ bet,
    const float* __restrict__ mu, const float* __restrict__ var,
    float* __restrict__ out)
{
    int n = blockIdx.x;
    int tid = threadIdx.x;
    int beg = g_off[n];
    int deg = g_off[n + 1] - beg;
    __shared__ float w_sh[256];
    __shared__ int   src_sh[64];
    __shared__ float red[128];
    __shared__ float inv_s[4];

    int ch = tid >> 2;
    int hh = tid & 3;
    int my_h = tid >> 5;
    int c = tid * 2;
    float adv = ad[n * 4 + hh];

    float accx = 0.f, accy = 0.f, wsum = 0.f;

    for (int b0 = 0; b0 < deg; b0 += 64) {
        __syncthreads();
        #pragma unroll
        for (int q = 0; q < 2; q++) {
            int slot = ch + q * 32;
            int i = b0 + slot;
            if (i < deg) {
                int s = g_csr_src[beg + i];
                float l = as[s * 4 + hh] + adv;
                l = (l > 0.f) ? l : 0.2f * l;
                float w = __expf(l);
                w_sh[slot * 4 + hh] = w;
                wsum += w;
                if (hh == 0) src_sh[slot] = s;
            }
        }
        __syncthreads();
        int lim = min(64, deg - b0);
        for (int j = 0; j < lim; j++) {
            int s = src_sh[j];
            float w = w_sh[j * 4 + my_h];
            float2 hv = *reinterpret_cast<const float2*>(H + (size_t)s * 256 + c);
            accx += w * hv.x;
            accy += w * hv.y;
        }
    }

    red[tid] = wsum; __syncthreads();
    #pragma unroll
    for (int s = 64; s >= 4; s >>= 1) {
        if (tid < s) red[tid] += red[tid + s];
        __syncthreads();
    }
    if (tid < 4) inv_s[tid] = 1.f / (red[tid] + 1e-16f);
    __syncthreads();
    float iv = inv_s[my_h];

    float v0 = accx * iv + bias[c];
    float v1 = accy * iv + bias[c + 1];
    v0 = (v0 > 0.f) ? v0 : (__expf(v0) - 1.f);
    v1 = (v1 > 0.f) ? v1 : (__expf(v1) - 1.f);
    float sc0 = gam[c]     * rsqrtf(var[c]     + 1e-5f);
    float sc1 = gam[c + 1] * rsqrtf(var[c + 1] + 1e-5f);
    v0 = sc0 * (v0 - mu[c])     + bet[c];
    v1 = sc1 * (v1 - mu[c + 1]) + bet[c + 1];
    out[(size_t)n * 256 + c]     = v0;
    out[(size_t)n * 256 + c + 1] = v1;
}

// ---------------------------------------------------------------------------
// Final layer: heads=1, C=64, single pass, + bias, log_softmax. 64 thr/node.
// ---------------------------------------------------------------------------
__global__ void __launch_bounds__(64) agg_fin(
    const float* __restrict__ H, const float* __restrict__ as,
    const float* __restrict__ ad, const float* __restrict__ bias,
    float* __restrict__ out)
{
    int n = blockIdx.x, tid = threadIdx.x;
    int beg = g_off[n];
    int deg = g_off[n + 1] - beg;
    __shared__ float red[64];
    __shared__ float w_sh[64];
    __shared__ int   src_sh[64];
    float adv = ad[n];

    float acc = 0.f, wsum = 0.f;
    for (int b0 = 0; b0 < deg; b0 += 64) {
        int i = b0 + tid;
        __syncthreads();
        if (i < deg) {
            int s = g_csr_src[beg + i];
            float l = as[s] + adv; l = (l > 0.f) ? l : 0.2f * l;
            float w = __expf(l);
            w_sh[tid] = w;
            src_sh[tid] = s;
            wsum += w;
        }
        __syncthreads();
        int lim = min(64, deg - b0);
        for (int j = 0; j < lim; j++)
            acc += w_sh[j] * H[(size_t)src_sh[j] * 64 + tid];
    }

    red[tid] = wsum; __syncthreads();
    #pragma unroll
    for (int s = 32; s >= 1; s >>= 1) {
        if (tid < s) red[tid] += red[tid + s];
        __syncthreads();
    }
    float iv = 1.f / (red[0] + 1e-16f);
    __syncthreads();

    float z = acc * iv + bias[tid];

    red[tid] = z; __syncthreads();
    #pragma unroll
    for (int s = 32; s >= 1; s >>= 1) {
        if (tid < s) red[tid] = fmaxf(red[tid], red[tid + s]);
        __syncthreads();
    }
    float zm = red[0]; __syncthreads();
    red[tid] = __expf(z - zm); __syncthreads();
    #pragma unroll
    for (int s = 32; s >= 1; s >>= 1) {
        if (tid < s) red[tid] += red[tid + s];
        __syncthreads();
    }
    float lse = zm + logf(red[0]);
    out[(size_t)n * 64 + tid] = z - lse;
}

// ---------------------------------------------------------------------------
extern "C" void kernel_launch(void* const* d_in, const int* in_sizes, int n_in,
                              void* d_out, int out_size)
{
    const float* x    = (const float*)d_in[0];
    const int*   ei   = (const int*)  d_in[1];
    const float* W0   = (const float*)d_in[2];
    const float* as0w = (const float*)d_in[3];
    const float* ad0w = (const float*)d_in[4];
    const float* b0   = (const float*)d_in[5];
    const float* gm0  = (const float*)d_in[6];
    const float* be0  = (const float*)d_in[7];
    const float* mu0  = (const float*)d_in[8];
    const float* vr0  = (const float*)d_in[9];
    const float* W1   = (const float*)d_in[10];
    const float* as1w = (const float*)d_in[11];
    const float* ad1w = (const float*)d_in[12];
    const float* b1   = (const float*)d_in[13];
    const float* gm1  = (const float*)d_in[14];
    const float* be1  = (const float*)d_in[15];
    const float* mu1  = (const float*)d_in[16];
    const float* vr1  = (const float*)d_in[17];
    const float* W2   = (const float*)d_in[18];
    const float* as2w = (const float*)d_in[19];
    const float* ad2w = (const float*)d_in[20];
    const float* b2   = (const float*)d_in[21];

    int N = in_sizes[0] / 128;      // 10000
    int E = in_sizes[1] / 2;        // 320000
    int Etot = E + N;

    float *H, *X, *AS, *AD;
    cudaGetSymbolAddress((void**)&H,  g_H);
    cudaGetSymbolAddress((void**)&X,  g_X);
    cudaGetSymbolAddress((void**)&AS, g_as);
    cudaGetSymbolAddress((void**)&AD, g_ad);

    static cudaStream_t s2 = nullptr;
    static cudaEvent_t evFork = nullptr, evJoin = nullptr;
    if (!s2) {
        cudaStreamCreateWithFlags(&s2, cudaStreamNonBlocking);
        cudaEventCreateWithFlags(&evFork, cudaEventDisableTiming);
        cudaEventCreateWithFlags(&evJoin, cudaEventDisableTiming);
    }

    // fork: CSR build on s2, GEMM0 on main stream, join before agg4
    cudaEventRecord(evFork, 0);
    cudaStreamWaitEvent(s2, evFork, 0);
    zero_cnt<<<(N + 255) / 256, 256, 0, s2>>>(N);
    hist_k<<<(Etot + 255) / 256, 256, 0, s2>>>(ei, E, Etot);
    scan_k<<<1, 1024, 0, s2>>>(N, Etot);
    scatter_k<<<(Etot + 255) / 256, 256, 0, s2>>>(ei, E, Etot);
    cudaEventRecord(evJoin, s2);

    // layer 0: 128 -> 4x64 concat (GEMM concurrent with CSR build)
    gemm128att<<<dim3((N + 127) / 128, 2), 256>>>(x, W0, H, as0w, ad0w, AS, AD, N, 256, 128, 4);
    cudaStreamWaitEvent(0, evJoin, 0);
    agg4<<<N, 128>>>(H, AS, AD, b0, gm0, be0, mu0, vr0, X);

    // layer 1: 256 -> 4x64 concat
    gemm128att<<<dim3((N + 127) / 128, 2), 256>>>(X, W1, H, as1w, ad1w, AS, AD, N, 256, 256, 4);
    agg4<<<N, 128>>>(H, AS, AD, b1, gm1, be1, mu1, vr1, X);

    // layer 2: 256 -> 64, heads=1, + log_softmax
    gemm64att<<<dim3((N + 63) / 64, 1), 128>>>(X, W2, H, as2w, ad2w, AS, AD, N, 64, 256, 1);
    agg_fin<<<N, 64>>>(H, AS, AD, b2, (float*)d_out);
}

// round 7
// speedup vs baseline: 1.2381x; 1.2381x over previous
#include <cuda_runtime.h>

// ---------------------------------------------------------------------------
// GAT 3-layer forward. CSR build overlapped with layer-0 GEMM on a side
// stream; per layer: GEMM(+fused att dots) -> single-pass aggregation.
// 64x64 GEMM tile / 128 threads (628-block grid: best wave shape at M=10000).
// ---------------------------------------------------------------------------

#define MAXN 10240
#define MAXE 340000

__device__ float g_H[MAXN * 256];
__device__ float g_X[MAXN * 256];
__device__ float g_as[MAXN * 4];
__device__ float g_ad[MAXN * 4];
__device__ int   g_cnt[MAXN];
__device__ int   g_off[MAXN + 1];
__device__ int   g_wp[MAXN];
__device__ int   g_csr_src[MAXE];

// ---------------------------------------------------------------------------
// GEMM: C = A@B. 64x64 block tile, 128 threads, 8x4 per thread, BK=16,
// register prefetch. Fused attention-dot epilogue (block col range == head).
// ---------------------------------------------------------------------------
__global__ void __launch_bounds__(128) gemm64att(
    const float* __restrict__ A, const float* __restrict__ B,
    float* __restrict__ C,
    const float* __restrict__ asw, const float* __restrict__ adw,
    float* __restrict__ as_o, float* __restrict__ ad_o,
    int M, int N, int K, int heads)
{
    __shared__ float As[16][68];
    __shared__ float Bs[16][68];
    int tid = threadIdx.x;          // 128
    int tx = tid & 15, ty = tid >> 4;
    int row0 = blockIdx.x * 64, col0 = blockIdx.y * 64;

    int ar0 = tid >> 2,          akq0 = (tid & 3) * 4;
    int ar1 = (tid + 128) >> 2,  akq1 = ((tid + 128) & 3) * 4;
    int bk0 = tid >> 4,          bcq0 = (tid & 15) * 4;
    int bk1 = (tid + 128) >> 4,  bcq1 = bcq0;

    float4 ap0, ap1, bp0, bp1;
    {
        int g0 = row0 + ar0, g1 = row0 + ar1;
        ap0 = (g0 < M) ? *reinterpret_cast<const float4*>(A + (size_t)g0 * K + akq0)
                       : make_float4(0.f, 0.f, 0.f, 0.f);
        ap1 = (g1 < M) ? *reinterpret_cast<const float4*>(A + (size_t)g1 * K + akq1)
                       : make_float4(0.f, 0.f, 0.f, 0.f);
        bp0 = *reinterpret_cast<const float4*>(B + (size_t)bk0 * N + col0 + bcq0);
        bp1 = *reinterpret_cast<const float4*>(B + (size_t)bk1 * N + col0 + bcq1);
    }

    float acc[8][4] = {};

    for (int k0 = 0; k0 < K; k0 += 16) {
        As[akq0 + 0][ar0] = ap0.x; As[akq0 + 1][ar0] = ap0.y;
        As[akq0 + 2][ar0] = ap0.z; As[akq0 + 3][ar0] = ap0.w;
        As[akq1 + 0][ar1] = ap1.x; As[akq1 + 1][ar1] = ap1.y;
        As[akq1 + 2][ar1] = ap1.z; As[akq1 + 3][ar1] = ap1.w;
        *reinterpret_cast<float4*>(&Bs[bk0][bcq0]) = bp0;
        *reinterpret_cast<float4*>(&Bs[bk1][bcq1]) = bp1;
        __syncthreads();

        if (k0 + 16 < K) {
            int g0 = row0 + ar0, g1 = row0 + ar1;
            int kn = k0 + 16;
            ap0 = (g0 < M) ? *reinterpret_cast<const float4*>(A + (size_t)g0 * K + kn + akq0)
                           : make_float4(0.f, 0.f, 0.f, 0.f);
            ap1 = (g1 < M) ? *reinterpret_cast<const float4*>(A + (size_t)g1 * K + kn + akq1)
                           : make_float4(0.f, 0.f, 0.f, 0.f);
            bp0 = *reinterpret_cast<const float4*>(B + (size_t)(kn + bk0) * N + col0 + bcq0);
            bp1 = *reinterpret_cast<const float4*>(B + (size_t)(kn + bk1) * N + col0 + bcq1);
        }

        #pragma unroll
        for (int kk = 0; kk < 16; kk++) {
            float4 a0 = *reinterpret_cast<const float4*>(&As[kk][ty * 8]);
            float4 a1 = *reinterpret_cast<const float4*>(&As[kk][ty * 8 + 4]);
            float4 b4 = *reinterpret_cast<const float4*>(&Bs[kk][tx * 4]);
            float av[8] = {a0.x, a0.y, a0.z, a0.w, a1.x, a1.y, a1.z, a1.w};
            float bv[4] = {b4.x, b4.y, b4.z, b4.w};
            #pragma unroll
            for (int i = 0; i < 8; i++)
                #pragma unroll
                for (int j = 0; j < 4; j++)
                    acc[i][j] += av[i] * bv[j];
        }
        __syncthreads();
    }

    #pragma unroll
    for (int i = 0; i < 8; i++) {
        int gr = row0 + ty * 8 + i;
        if (gr < M) {
            float4 v = make_float4(acc[i][0], acc[i][1], acc[i][2], acc[i][3]);
            *reinterpret_cast<float4*>(C + (size_t)gr * N + col0 + tx * 4) = v;
        }
    }

    float asv[4], adv_[4];
    #pragma unroll
    for (int j = 0; j < 4; j++) {
        asv[j]  = asw[col0 + tx * 4 + j];
        adv_[j] = adw[col0 + tx * 4 + j];
    }
    int h = blockIdx.y;
    #pragma unroll
    for (int i = 0; i < 8; i++) {
        float ss = 0.f, sd = 0.f;
        #pragma unroll
        for (int j = 0; j < 4; j++) {
            ss += acc[i][j] * asv[j];
            sd += acc[i][j] * adv_[j];
        }
        #pragma unroll
        for (int o = 1; o <= 8; o <<= 1) {
            ss += __shfl_xor_sync(0xffffffffu, ss, o);
            sd += __shfl_xor_sync(0xffffffffu, sd, o);
        }
        if (tx == 0) {
            int gr = row0 + ty * 8 + i;
            if (gr < M) {
                as_o[gr * heads + h] = ss;
                ad_o[gr * heads + h] = sd;
            }
        }
    }
}

// ---------------------------------------------------------------------------
// CSR build
// ---------------------------------------------------------------------------
__global__ void zero_cnt(int N)
{
    int i = blockIdx.x * blockDim.x + threadIdx.x;
    if (i < N) g_cnt[i] = 0;
}

__global__ void hist_k(const int* __restrict__ ei, int E, int Etot)
{
    int e = blockIdx.x * blockDim.x + threadIdx.x;
    if (e >= Etot) return;
    int d = (e < E) ? ei[E + e] : (e - E);
    atomicAdd(&g_cnt[d], 1);
}

__global__ void scan_k(int N, int Etot)
{
    __shared__ int wsum[32];
    int tid = threadIdx.x;
    const int PER = 12;
    int base = tid * PER;
    int loc[PER];
    int s = 0;
    #pragma unroll
    for (int i = 0; i < PER; i++) {
        int idx = base + i;
        int v = (idx < N) ? g_cnt[idx] : 0;
        loc[i] = s; s += v;
    }
    int lane = tid & 31, wid = tid >> 5;
    int x = s;
    #pragma unroll
    for (int o = 1; o < 32; o <<= 1) {
        int y = __shfl_up_sync(0xffffffffu, x, o);
        if (lane >= o) x += y;
    }
    if (lane == 31) wsum[wid] = x;
    __syncthreads();
    if (wid == 0) {
        int w = wsum[lane];
        #pragma unroll
        for (int o = 1; o < 32; o <<= 1) {
            int y = __shfl_up_sync(0xffffffffu, w, o);
            if (lane >= o) w += y;
        }
        wsum[lane] = w;
    }
    __syncthreads();
    int excl = x - s + (wid ? wsum[wid - 1] : 0);
    #pragma unroll
    for (int i = 0; i < PER; i++) {
        int idx = base + i;
        if (idx < N) { int v = excl + loc[i]; g_off[idx] = v; g_wp[idx] = v; }
    }
    if (tid == 0) g_off[N] = Etot;
}

__global__ void scatter_k(const int* __restrict__ ei, int E, int Etot)
{
    int e = blockIdx.x * blockDim.x + threadIdx.x;
    if (e >= Etot) return;
    int sIdx, d;
    if (e < E) { sIdx = ei[e]; d = ei[E + e]; } else { sIdx = d = e - E; }
    int pos = atomicAdd(&g_wp[d], 1);
    g_csr_src[pos] = sIdx;
}

// ---------------------------------------------------------------------------
// Single-pass aggregation, heads=4, C=64 (256 ch). One block/node, 128 thr.
// Gather loop 2-way unrolled with independent accumulator pairs.
// ---------------------------------------------------------------------------
__global__ void __launch_bounds__(128) agg4(
    const float* __restrict__ H, const float* __restrict__ as,
    const float* __restrict__ ad, const float* __restrict__ bias,
    const float* __restrict__ gam, const float* __restrict__ bet,
    const float* __restrict__ mu, const float* __restrict__ var,
    float* __restrict__ out)
{
    int n = blockIdx.x;
    int tid = threadIdx.x;
    int beg = g_off[n];
    int deg = g_off[n + 1] - beg;
    __shared__ float w_sh[256];
    __shared__ int   src_sh[64];
    __shared__ float red[128];
    __shared__ float inv_s[4];

    int ch = tid >> 2;
    int hh = tid & 3;
    int my_h = tid >> 5;
    int c = tid * 2;
    float adv = ad[n * 4 + hh];

    float a0x = 0.f, a0y = 0.f, a1x = 0.f, a1y = 0.f;
    float wsum = 0.f;

    for (int b0 = 0; b0 < deg; b0 += 64) {
        __syncthreads();
        #pragma unroll
        for (int q = 0; q < 2; q++) {
            int slot = ch + q * 32;
            int i = b0 + slot;
            if (i < deg) {
                int s = g_csr_src[beg + i];
                float l = as[s * 4 + hh] + adv;
                l = (l > 0.f) ? l : 0.2f * l;
                float w = __expf(l);
                w_sh[slot * 4 + hh] = w;
                wsum += w;
                if (hh == 0) src_sh[slot] = s;
            }
        }
        __syncthreads();
        int lim = min(64, deg - b0);
        int j = 0;
        for (; j + 2 <= lim; j += 2) {
            int s0 = src_sh[j];
            int s1 = src_sh[j + 1];
            float w0 = w_sh[j * 4 + my_h];
            float w1 = w_sh[(j + 1) * 4 + my_h];
            float2 h0 = __ldg(reinterpret_cast<const float2*>(H + (size_t)s0 * 256 + c));
            float2 h1 = __ldg(reinterpret_cast<const float2*>(H + (size_t)s1 * 256 + c));
            a0x += w0 * h0.x;  a0y += w0 * h0.y;
            a1x += w1 * h1.x;  a1y += w1 * h1.y;
        }
        if (j < lim) {
            int s0 = src_sh[j];
            float w0 = w_sh[j * 4 + my_h];
            float2 h0 = __ldg(reinterpret_cast<const float2*>(H + (size_t)s0 * 256 + c));
            a0x += w0 * h0.x;  a0y += w0 * h0.y;
        }
    }
    float accx = a0x + a1x;
    float accy = a0y + a1y;

    red[tid] = wsum; __syncthreads();
    #pragma unroll
    for (int s = 64; s >= 4; s >>= 1) {
        if (tid < s) red[tid] += red[tid + s];
        __syncthreads();
    }
    if (tid < 4) inv_s[tid] = 1.f / (red[tid] + 1e-16f);
    __syncthreads();
    float iv = inv_s[my_h];

    float v0 = accx * iv + bias[c];
    float v1 = accy * iv + bias[c + 1];
    v0 = (v0 > 0.f) ? v0 : (__expf(v0) - 1.f);
    v1 = (v1 > 0.f) ? v1 : (__expf(v1) - 1.f);
    float sc0 = gam[c]     * rsqrtf(var[c]     + 1e-5f);
    float sc1 = gam[c + 1] * rsqrtf(var[c + 1] + 1e-5f);
    v0 = sc0 * (v0 - mu[c])     + bet[c];
    v1 = sc1 * (v1 - mu[c + 1]) + bet[c + 1];
    out[(size_t)n * 256 + c]     = v0;
    out[(size_t)n * 256 + c + 1] = v1;
}

// ---------------------------------------------------------------------------
// Final layer: heads=1, C=64, single pass, + bias, log_softmax. 64 thr/node.
// ---------------------------------------------------------------------------
__global__ void __launch_bounds__(64) agg_fin(
    const float* __restrict__ H, const float* __restrict__ as,
    const float* __restrict__ ad, const float* __restrict__ bias,
    float* __restrict__ out)
{
    int n = blockIdx.x, tid = threadIdx.x;
    int beg = g_off[n];
    int deg = g_off[n + 1] - beg;
    __shared__ float red[64];
    __shared__ float w_sh[64];
    __shared__ int   src_sh[64];
    float adv = ad[n];

    float acc0 = 0.f, acc1 = 0.f, wsum = 0.f;
    for (int b0 = 0; b0 < deg; b0 += 64) {
        int i = b0 + tid;
        __syncthreads();
        if (i < deg) {
            int s = g_csr_src[beg + i];
            float l = as[s] + adv; l = (l > 0.f) ? l : 0.2f * l;
            float w = __expf(l);
            w_sh[tid] = w;
            src_sh[tid] = s;
            wsum += w;
        }
        __syncthreads();
        int lim = min(64, deg - b0);
        int j = 0;
        for (; j + 2 <= lim; j += 2) {
            acc0 += w_sh[j]     * __ldg(H + (size_t)src_sh[j]     * 64 + tid);
            acc1 += w_sh[j + 1] * __ldg(H + (size_t)src_sh[j + 1] * 64 + tid);
        }
        if (j < lim)
            acc0 += w_sh[j] * __ldg(H + (size_t)src_sh[j] * 64 + tid);
    }
    float acc = acc0 + acc1;

    red[tid] = wsum; __syncthreads();
    #pragma unroll
    for (int s = 32; s >= 1; s >>= 1) {
        if (tid < s) red[tid] += red[tid + s];
        __syncthreads();
    }
    float iv = 1.f / (red[0] + 1e-16f);
    __syncthreads();

    float z = acc * iv + bias[tid];

    red[tid] = z; __syncthreads();
    #pragma unroll
    for (int s = 32; s >= 1; s >>= 1) {
        if (tid < s) red[tid] = fmaxf(red[tid], red[tid + s]);
        __syncthreads();
    }
    float zm = red[0]; __syncthreads();
    red[tid] = __expf(z - zm); __syncthreads();
    #pragma unroll
    for (int s = 32; s >= 1; s >>= 1) {
        if (tid < s) red[tid] += red[tid + s];
        __syncthreads();
    }
    float lse = zm + logf(red[0]);
    out[(size_t)n * 64 + tid] = z - lse;
}

// ---------------------------------------------------------------------------
extern "C" void kernel_launch(void* const* d_in, const int* in_sizes, int n_in,
                              void* d_out, int out_size)
{
    const float* x    = (const float*)d_in[0];
    const int*   ei   = (const int*)  d_in[1];
    const float* W0   = (const float*)d_in[2];
    const float* as0w = (const float*)d_in[3];
    const float* ad0w = (const float*)d_in[4];
    const float* b0   = (const float*)d_in[5];
    const float* gm0  = (const float*)d_in[6];
    const float* be0  = (const float*)d_in[7];
    const float* mu0  = (const float*)d_in[8];
    const float* vr0  = (const float*)d_in[9];
    const float* W1   = (const float*)d_in[10];
    const float* as1w = (const float*)d_in[11];
    const float* ad1w = (const float*)d_in[12];
    const float* b1   = (const float*)d_in[13];
    const float* gm1  = (const float*)d_in[14];
    const float* be1  = (const float*)d_in[15];
    const float* mu1  = (const float*)d_in[16];
    const float* vr1  = (const float*)d_in[17];
    const float* W2   = (const float*)d_in[18];
    const float* as2w = (const float*)d_in[19];
    const float* ad2w = (const float*)d_in[20];
    const float* b2   = (const float*)d_in[21];

    int N = in_sizes[0] / 128;      // 10000
    int E = in_sizes[1] / 2;        // 320000
    int Etot = E + N;

    float *H, *X, *AS, *AD;
    cudaGetSymbolAddress((void**)&H,  g_H);
    cudaGetSymbolAddress((void**)&X,  g_X);
    cudaGetSymbolAddress((void**)&AS, g_as);
    cudaGetSymbolAddress((void**)&AD, g_ad);

    static cudaStream_t s2 = nullptr;
    static cudaEvent_t evFork = nullptr, evJoin = nullptr;
    if (!s2) {
        cudaStreamCreateWithFlags(&s2, cudaStreamNonBlocking);
        cudaEventCreateWithFlags(&evFork, cudaEventDisableTiming);
        cudaEventCreateWithFlags(&evJoin, cudaEventDisableTiming);
    }

    // fork: CSR build on s2, GEMM0 on main stream, join before agg4
    cudaEventRecord(evFork, 0);
    cudaStreamWaitEvent(s2, evFork, 0);
    zero_cnt<<<(N + 255) / 256, 256, 0, s2>>>(N);
    hist_k<<<(Etot + 255) / 256, 256, 0, s2>>>(ei, E, Etot);
    scan_k<<<1, 1024, 0, s2>>>(N, Etot);
    scatter_k<<<(Etot + 255) / 256, 256, 0, s2>>>(ei, E, Etot);
    cudaEventRecord(evJoin, s2);

    // layer 0: 128 -> 4x64 concat (GEMM concurrent with CSR build)
    gemm64att<<<dim3((N + 63) / 64, 4), 128>>>(x, W0, H, as0w, ad0w, AS, AD, N, 256, 128, 4);
    cudaStreamWaitEvent(0, evJoin, 0);
    agg4<<<N, 128>>>(H, AS, AD, b0, gm0, be0, mu0, vr0, X);

    // layer 1: 256 -> 4x64 concat
    gemm64att<<<dim3((N + 63) / 64, 4), 128>>>(X, W1, H, as1w, ad1w, AS, AD, N, 256, 256, 4);
    agg4<<<N, 128>>>(H, AS, AD, b1, gm1, be1, mu1, vr1, X);

    // layer 2: 256 -> 64, heads=1, + log_softmax
    gemm64att<<<dim3((N + 63) / 64, 1), 128>>>(X, W2, H, as2w, ad2w, AS, AD, N, 64, 256, 1);
    agg_fin<<<N, 64>>>(H, AS, AD, b2, (float*)d_out);
}